// round 2
// baseline (speedup 1.0000x reference)
#include <cuda_runtime.h>

// Problem constants (fixed by the reference)
#define BN 16384   // number of segments/graphs (power of two)
#define FX 4       // node feature dim
#define ITEMS 32   // nodes per thread in the reduction pass

// Scratch accumulators (no cudaMalloc allowed) — 16384*4 + 16384 floats = 320KB
__device__ float g_sum[BN * FX];
__device__ float g_cnt[BN];

__global__ void zero_acc_kernel() {
    int i = blockIdx.x * blockDim.x + threadIdx.x;
    if (i < BN * FX) g_sum[i] = 0.0f;
    if (i < BN)      g_cnt[i] = 0.0f;
}

// Each thread handles a contiguous run of ITEMS nodes. batch is sorted, so we
// accumulate locally and only touch global atomics at segment boundaries.
// batch arrives as int32 (harness downcasts int64 inputs).
__global__ void seg_reduce_kernel(const float4* __restrict__ x,
                                  const int* __restrict__ batch,
                                  int n) {
    long long tid = (long long)blockIdx.x * blockDim.x + threadIdx.x;
    long long start = tid * ITEMS;
    if (start >= n) return;
    long long end = start + ITEMS;
    if (end > n) end = n;

    int cur = batch[start] & (BN - 1);
    float4 s = x[start];
    float  c = 1.0f;

    for (long long i = start + 1; i < end; ++i) {
        int    b = batch[i] & (BN - 1);
        float4 v = x[i];
        if (b != cur) {
            atomicAdd(&g_sum[cur * FX + 0], s.x);
            atomicAdd(&g_sum[cur * FX + 1], s.y);
            atomicAdd(&g_sum[cur * FX + 2], s.z);
            atomicAdd(&g_sum[cur * FX + 3], s.w);
            atomicAdd(&g_cnt[cur], c);
            cur = b;
            s = v;
            c = 1.0f;
        } else {
            s.x += v.x; s.y += v.y; s.z += v.z; s.w += v.w;
            c += 1.0f;
        }
    }
    atomicAdd(&g_sum[cur * FX + 0], s.x);
    atomicAdd(&g_sum[cur * FX + 1], s.y);
    atomicAdd(&g_sum[cur * FX + 2], s.z);
    atomicAdd(&g_sum[cur * FX + 3], s.w);
    atomicAdd(&g_cnt[cur], c);
}

// Tiny MLP: h = concat(u, mean) [5], leaky_relu(h@W1+b1, 0.1), @W2+b2 -> out[B,1]
__global__ void mlp_kernel(const float* __restrict__ u,
                           const float* __restrict__ W1,  // [5,5] row-major
                           const float* __restrict__ b1,  // [5]
                           const float* __restrict__ W2,  // [5,1]
                           const float* __restrict__ b2,  // [1]
                           float* __restrict__ out) {
    int i = blockIdx.x * blockDim.x + threadIdx.x;
    if (i >= BN) return;

    float cnt = g_cnt[i];
    float inv = (cnt > 0.0f) ? (1.0f / cnt) : 0.0f;

    float h[5];
    h[0] = u[i];
    #pragma unroll
    for (int f = 0; f < FX; ++f) h[1 + f] = g_sum[i * FX + f] * inv;

    float t[5];
    #pragma unroll
    for (int j = 0; j < 5; ++j) {
        float acc = __ldg(&b1[j]);
        #pragma unroll
        for (int k = 0; k < 5; ++k) acc += h[k] * __ldg(&W1[k * 5 + j]);
        t[j] = (acc > 0.0f) ? acc : 0.1f * acc;
    }

    float o = __ldg(&b2[0]);
    #pragma unroll
    for (int j = 0; j < 5; ++j) o += t[j] * __ldg(&W2[j]);

    out[i] = o;
}

extern "C" void kernel_launch(void* const* d_in, const int* in_sizes, int n_in,
                              void* d_out, int out_size) {
    const float* x     = (const float*)d_in[0];
    const int*   batch = (const int*)d_in[1];
    const float* u     = (const float*)d_in[2];
    const float* W1    = (const float*)d_in[3];
    const float* b1    = (const float*)d_in[4];
    const float* W2    = (const float*)d_in[5];
    const float* b2    = (const float*)d_in[6];
    float* out = (float*)d_out;

    int n = in_sizes[1];  // number of nodes (batch length)

    // 1) zero accumulators
    {
        int total = BN * FX;
        int threads = 256;
        int blocks = (total + threads - 1) / threads;
        zero_acc_kernel<<<blocks, threads>>>();
    }

    // 2) segment reduction
    {
        long long nthreads = ((long long)n + ITEMS - 1) / ITEMS;
        int threads = 256;
        int blocks = (int)((nthreads + threads - 1) / threads);
        seg_reduce_kernel<<<blocks, threads>>>((const float4*)x, batch, n);
    }

    // 3) MLP
    {
        int threads = 256;
        int blocks = (BN + threads - 1) / threads;
        mlp_kernel<<<blocks, threads>>>(u, W1, b1, W2, b2, out);
    }
}